// round 2
// baseline (speedup 1.0000x reference)
#include <cuda_runtime.h>
#include <math.h>

#define DEPTH 24
#define DM    192
#define DI    384
#define DS    16
#define DR    12
#define BATCH 4
#define LSEQ  401
#define NCLS  22
#define XD    44
#define EPSV  1e-5f
#define NC    32            // scan chunks
#define CL    13            // ceil(401/32)
#define ROWS  (BATCH*LSEQ)     // 1604
#define ROWS2 (2*BATCH*LSEQ)   // 3208

// ---------------- scratch ----------------------------------------------------
__device__ float g_res [ROWS*DM];
__device__ float g_hn  [ROWS*DM];
__device__ float g_xz  [ROWS*2*DI];
__device__ float g_dbl [ROWS2*XD];
__device__ float g_y   [ROWS2*DI];
__device__ float g_Aexp[2*DEPTH*DI*DS];
__device__ int   g_Aflag[2*DEPTH*DI];
__device__ float g_cwT [DEPTH*4*DI];
__device__ float g_hloc[2*BATCH*NC*DS*DI];
__device__ float g_S   [2*BATCH*NC*DI];

__device__ __forceinline__ float siluf(float x) { return x / (1.f + __expf(-x)); }
__device__ __forceinline__ float softplusf(float x) {
    return x > 20.f ? x : log1pf(__expf(x));
}

// ---------------- prep: A = -exp(A_log), geometric detect, conv transpose ----
__global__ void k_prep(const float* __restrict__ Alog, const float* __restrict__ Ablog,
                       const float* __restrict__ cw) {
    int i = blockIdx.x * blockDim.x + threadIdx.x;
    if (i >= 2 * DEPTH * DI) return;
    int dir = i / (DEPTH * DI);
    int rest = i - dir * (DEPTH * DI);
    const float* src = (dir ? Ablog : Alog) + (size_t)rest * DS;
    float A[DS];
#pragma unroll
    for (int n = 0; n < DS; n++) A[n] = -__expf(src[n]);
    float A0 = A[0];
    bool ok = true;
#pragma unroll
    for (int n = 1; n < DS; n++) {
        float tgt = (float)(n + 1) * A0;
        ok = ok && (fabsf(A[n] - tgt) <= 1e-4f * fabsf(tgt) + 1e-30f);
    }
#pragma unroll
    for (int n = 0; n < DS; n++) g_Aexp[(size_t)i * DS + n] = A[n];
    g_Aflag[i] = ok ? 1 : 0;
    if (i < DEPTH * DI) {
        int l = i / DI, d = i % DI;
#pragma unroll
        for (int j = 0; j < 4; j++)
            g_cwT[(size_t)l * 4 * DI + j * DI + d] = cw[((size_t)l * DI + d) * 4 + j];
    }
}

// ---------------- patch embed + cls + pos + layer-0 resnorm ------------------
__global__ void k_embed(const float* __restrict__ x, const float* __restrict__ pew,
                        const float* __restrict__ peb, const float* __restrict__ cls,
                        const float* __restrict__ pos, const float* __restrict__ nw0) {
    int t = blockIdx.x, b = blockIdx.y, c = threadIdx.x;
    float v;
    __shared__ float patch[256];
    __shared__ float red[6];
    if (t == 0) {
        v = cls[c] + pos[c];
    } else {
        int p = t - 1;
        int ph = p / 200, pw = p % 200;
        for (int i = c; i < 256; i += DM)
            patch[i] = x[(size_t)b * 32 * 3200 + (size_t)(ph * 16 + i / 16) * 3200
                         + pw * 16 + (i % 16)];
        __syncthreads();
        float acc = peb[c];
        const float* wc = pew + (size_t)c * 256;
#pragma unroll 8
        for (int i = 0; i < 256; i++) acc = fmaf(patch[i], __ldg(wc + i), acc);
        v = acc + pos[(size_t)t * DM + c];
    }
    float u = 2.f * v;                       // residual after layer-0 add
    size_t o = ((size_t)b * LSEQ + t) * DM + c;
    g_res[o] = u;
    float s = u * u;
#pragma unroll
    for (int ofs = 16; ofs > 0; ofs >>= 1) s += __shfl_xor_sync(0xffffffffu, s, ofs);
    if ((c & 31) == 0) red[c >> 5] = s;
    __syncthreads();
    float tot = red[0] + red[1] + red[2] + red[3] + red[4] + red[5];
    float rs = rsqrtf(tot / (float)DM + EPSV);
    g_hn[o] = u * rs * nw0[c];
}

// ---------------- generic SGEMM (in_proj): C[M,N] = A[M,K] @ W[N,K]^T --------
template <int BM, int BN, int BK, int TM, int TN>
__global__ __launch_bounds__((BM / TM) * (BN / TN))
void sgemm_nt(const float* __restrict__ A, const float* __restrict__ W,
              float* __restrict__ C, int M, int N, int K) {
    constexpr int THR = (BM / TM) * (BN / TN);
    __shared__ float As[BK][BM + 4];
    __shared__ float Ws[BK][BN + 4];
    int tid = threadIdx.x;
    int tx = tid % (BN / TN);
    int ty = tid / (BN / TN);
    int row0 = blockIdx.y * BM;
    int col0 = blockIdx.x * BN;
    float acc[TM][TN];
#pragma unroll
    for (int i = 0; i < TM; i++)
#pragma unroll
        for (int j = 0; j < TN; j++) acc[i][j] = 0.f;

    for (int k0 = 0; k0 < K; k0 += BK) {
        for (int i = tid; i < BM * (BK / 4); i += THR) {
            int m = i / (BK / 4), kq = i % (BK / 4);
            float4 v = make_float4(0.f, 0.f, 0.f, 0.f);
            if (row0 + m < M)
                v = __ldg((const float4*)(A + (size_t)(row0 + m) * K + k0 + kq * 4));
            As[kq * 4 + 0][m] = v.x; As[kq * 4 + 1][m] = v.y;
            As[kq * 4 + 2][m] = v.z; As[kq * 4 + 3][m] = v.w;
        }
        for (int i = tid; i < BN * (BK / 4); i += THR) {
            int n = i / (BK / 4), kq = i % (BK / 4);
            float4 v = make_float4(0.f, 0.f, 0.f, 0.f);
            if (col0 + n < N)
                v = __ldg((const float4*)(W + (size_t)(col0 + n) * K + k0 + kq * 4));
            Ws[kq * 4 + 0][n] = v.x; Ws[kq * 4 + 1][n] = v.y;
            Ws[kq * 4 + 2][n] = v.z; Ws[kq * 4 + 3][n] = v.w;
        }
        __syncthreads();
#pragma unroll
        for (int k = 0; k < BK; k++) {
            float ra[TM], rb[TN];
#pragma unroll
            for (int i = 0; i < TM; i++) ra[i] = As[k][ty * TM + i];
#pragma unroll
            for (int j = 0; j < TN; j++) rb[j] = Ws[k][tx * TN + j];
#pragma unroll
            for (int i = 0; i < TM; i++)
#pragma unroll
                for (int j = 0; j < TN; j++) acc[i][j] = fmaf(ra[i], rb[j], acc[i][j]);
        }
        __syncthreads();
    }
#pragma unroll
    for (int i = 0; i < TM; i++) {
        int r = row0 + ty * TM + i;
        if (r >= M) continue;
#pragma unroll
        for (int j = 0; j < TN; j++) {
            int cc = col0 + tx * TN + j;
            if (cc < N) C[(size_t)r * N + cc] = acc[i][j];
        }
    }
}

// ---------------- x_proj GEMM with fused causal conv + silu on A -------------
// dbl[r, n] = silu(conv(xz_x))[r] . xpw[n, :],  r over 2*B*L, n < 44
#define DB_BM 32
#define DB_BN 48
#define DB_BK 16
__global__ __launch_bounds__(256)
void k_gemm_dbl(const float* __restrict__ xpw, const float* __restrict__ cwT,
                const float* __restrict__ cbl) {
    __shared__ float As[DB_BK][DB_BM + 4];
    __shared__ float Ws[DB_BK][DB_BN + 4];
    int tid = threadIdx.x;
    int tx = tid % 16;          // BN/TN = 48/3
    int ty = tid / 16;          // BM/TM = 32/2
    int row0 = blockIdx.y * DB_BM;
    float acc[2][3] = {};

    for (int k0 = 0; k0 < DI; k0 += DB_BK) {
        // A: conv + silu, 128 float4 tasks
        if (tid < DB_BM * (DB_BK / 4)) {
            int m = tid / 4, kq = tid % 4;
            int r = row0 + m;
            float4 a = make_float4(0.f, 0.f, 0.f, 0.f);
            if (r < ROWS2) {
                int dir = r / ROWS;
                int rem = r - dir * ROWS;
                int b = rem / LSEQ, t = rem % LSEQ;
                int d0 = k0 + kq * 4;
                float4 cb4 = *(const float4*)(cbl + d0);
                a = cb4;
                const float* xzb = g_xz + (size_t)b * LSEQ * 2 * DI + d0;
#pragma unroll
                for (int j = 0; j < 4; j++) {
                    if (t >= 3 - j) {
                        int tt = dir ? (LSEQ - 1 - t + 3 - j) : (t - (3 - j));
                        float4 x4 = __ldg((const float4*)(xzb + (size_t)tt * 2 * DI));
                        float4 w4 = __ldg((const float4*)(cwT + j * DI + d0));
                        a.x = fmaf(w4.x, x4.x, a.x); a.y = fmaf(w4.y, x4.y, a.y);
                        a.z = fmaf(w4.z, x4.z, a.z); a.w = fmaf(w4.w, x4.w, a.w);
                    }
                }
                a.x = siluf(a.x); a.y = siluf(a.y); a.z = siluf(a.z); a.w = siluf(a.w);
            }
            As[kq * 4 + 0][m] = a.x; As[kq * 4 + 1][m] = a.y;
            As[kq * 4 + 2][m] = a.z; As[kq * 4 + 3][m] = a.w;
        }
        // W: 192 float4 tasks
        if (tid < DB_BN * (DB_BK / 4)) {
            int n = tid / 4, kq = tid % 4;
            float4 v = make_float4(0.f, 0.f, 0.f, 0.f);
            if (n < XD)
                v = __ldg((const float4*)(xpw + (size_t)n * DI + k0 + kq * 4));
            Ws[kq * 4 + 0][n] = v.x; Ws[kq * 4 + 1][n] = v.y;
            Ws[kq * 4 + 2][n] = v.z; Ws[kq * 4 + 3][n] = v.w;
        }
        __syncthreads();
#pragma unroll
        for (int k = 0; k < DB_BK; k++) {
            float ra0 = As[k][ty * 2 + 0], ra1 = As[k][ty * 2 + 1];
            float rb0 = Ws[k][tx * 3 + 0], rb1 = Ws[k][tx * 3 + 1], rb2 = Ws[k][tx * 3 + 2];
            acc[0][0] = fmaf(ra0, rb0, acc[0][0]); acc[0][1] = fmaf(ra0, rb1, acc[0][1]);
            acc[0][2] = fmaf(ra0, rb2, acc[0][2]);
            acc[1][0] = fmaf(ra1, rb0, acc[1][0]); acc[1][1] = fmaf(ra1, rb1, acc[1][1]);
            acc[1][2] = fmaf(ra1, rb2, acc[1][2]);
        }
        __syncthreads();
    }
#pragma unroll
    for (int i = 0; i < 2; i++) {
        int r = row0 + ty * 2 + i;
        if (r >= ROWS2) continue;
#pragma unroll
        for (int j = 0; j < 3; j++) {
            int n = tx * 3 + j;
            if (n < XD) g_dbl[(size_t)r * XD + n] = acc[i][j];
        }
    }
}

// ---------------- out_proj GEMM: fused gate on A, fused res+rmsnorm epilogue -
// A[r,k] = (yf + yb) * silu(z);  C = A @ opw^T ; then res += C, hn = rmsnorm
#define OG_BM 16
#define OG_BN 192
#define OG_BK 16
__global__ __launch_bounds__(256)
void k_gemm_out(const float* __restrict__ opw, const float* __restrict__ nw) {
    __shared__ float As[OG_BK][OG_BM + 4];
    __shared__ float Ws[OG_BK][OG_BN + 4];
    int tid = threadIdx.x;
    int tx = tid % 32;         // BN/TN = 192/6
    int ty = tid / 32;         // BM/TM = 16/2
    int row0 = blockIdx.y * OG_BM;
    float acc[2][6] = {};

    for (int k0 = 0; k0 < DI; k0 += OG_BK) {
        if (tid < OG_BM * (OG_BK / 4)) {     // 64 tasks
            int m = tid / 4, kq = tid % 4;
            int r = row0 + m;
            float4 a = make_float4(0.f, 0.f, 0.f, 0.f);
            if (r < ROWS) {
                int b = r / LSEQ, t = r % LSEQ;
                int d0 = k0 + kq * 4;
                float4 yf = __ldg((const float4*)(g_y + (size_t)r * DI + d0));
                size_t rb = ((size_t)(BATCH + b) * LSEQ + (LSEQ - 1 - t));
                float4 yb = __ldg((const float4*)(g_y + rb * DI + d0));
                float4 z4 = __ldg((const float4*)(g_xz + (size_t)r * 2 * DI + DI + d0));
                a.x = (yf.x + yb.x) * siluf(z4.x);
                a.y = (yf.y + yb.y) * siluf(z4.y);
                a.z = (yf.z + yb.z) * siluf(z4.z);
                a.w = (yf.w + yb.w) * siluf(z4.w);
            }
            As[kq * 4 + 0][m] = a.x; As[kq * 4 + 1][m] = a.y;
            As[kq * 4 + 2][m] = a.z; As[kq * 4 + 3][m] = a.w;
        }
        for (int i = tid; i < OG_BN * (OG_BK / 4); i += 256) {   // 768 tasks
            int n = i / 4, kq = i % 4;
            float4 v = __ldg((const float4*)(opw + (size_t)n * DI + k0 + kq * 4));
            Ws[kq * 4 + 0][n] = v.x; Ws[kq * 4 + 1][n] = v.y;
            Ws[kq * 4 + 2][n] = v.z; Ws[kq * 4 + 3][n] = v.w;
        }
        __syncthreads();
#pragma unroll
        for (int k = 0; k < OG_BK; k++) {
            float ra[2], rb[6];
            ra[0] = As[k][ty * 2 + 0]; ra[1] = As[k][ty * 2 + 1];
#pragma unroll
            for (int j = 0; j < 6; j++) rb[j] = Ws[k][tx * 6 + j];
#pragma unroll
            for (int i = 0; i < 2; i++)
#pragma unroll
                for (int j = 0; j < 6; j++) acc[i][j] = fmaf(ra[i], rb[j], acc[i][j]);
        }
        __syncthreads();
    }
    // epilogue: v = res + acc; res = v; hn = rmsnorm(v) * nw  (row = 192 = one warp)
#pragma unroll
    for (int i = 0; i < 2; i++) {
        int r = row0 + ty * 2 + i;
        float v[6];
        float s = 0.f;
        bool valid = (r < ROWS);
#pragma unroll
        for (int j = 0; j < 6; j++) {
            int c = tx * 6 + j;
            if (valid) {
                v[j] = g_res[(size_t)r * DM + c] + acc[i][j];
                g_res[(size_t)r * DM + c] = v[j];
                s += v[j] * v[j];
            }
        }
#pragma unroll
        for (int ofs = 16; ofs > 0; ofs >>= 1) s += __shfl_xor_sync(0xffffffffu, s, ofs);
        float rs = rsqrtf(s / (float)DM + EPSV);
        if (valid) {
#pragma unroll
            for (int j = 0; j < 6; j++) {
                int c = tx * 6 + j;
                g_hn[(size_t)r * DM + c] = v[j] * rs * __ldg(nw + c);
            }
        }
    }
}

// ---------------- scan pass A: chunk-local scan (conv + dt_proj fused) -------
__global__ __launch_bounds__(DI)
void k_scanA(const float* __restrict__ dtw, const float* __restrict__ dtb,
             const float* __restrict__ Dpl, const float* __restrict__ cwl,
             const float* __restrict__ cbl, int l) {
    int dir = blockIdx.z, b = blockIdx.y, c = blockIdx.x;
    int d = threadIdx.x;
    const float* Ap = g_Aexp + (((size_t)dir * DEPTH + l) * DI + d) * DS;
    float A[DS];
#pragma unroll
    for (int n = 0; n < DS; n++) A[n] = Ap[n];
    int flag = g_Aflag[((size_t)dir * DEPTH + l) * DI + d];
    float A0 = A[0];
    float wdt[DR];
#pragma unroll
    for (int j = 0; j < DR; j++) wdt[j] = __ldg(dtw + (size_t)d * DR + j);
    float db0 = dtb[d], Dd = Dpl[d];
    float w0 = cwl[d * 4 + 0], w1 = cwl[d * 4 + 1],
          w2 = cwl[d * 4 + 2], w3 = cwl[d * 4 + 3];
    float cbd = cbl[d];
    const float* xz_d = g_xz + (size_t)b * LSEQ * 2 * DI + d;

    size_t r0 = ((size_t)dir * BATCH + b) * LSEQ;
    int t0 = c * CL, t1 = min(LSEQ, t0 + CL);
    float h[DS];
#pragma unroll
    for (int n = 0; n < DS; n++) h[n] = 0.f;
    float S = 0.f;

    for (int t = t0; t < t1; t++) {
        // conv + silu -> xv
        float cs = cbd;
        if (dir == 0) {
            if (t >= 3) cs = fmaf(w0, xz_d[(size_t)(t - 3) * 2 * DI], cs);
            if (t >= 2) cs = fmaf(w1, xz_d[(size_t)(t - 2) * 2 * DI], cs);
            if (t >= 1) cs = fmaf(w2, xz_d[(size_t)(t - 1) * 2 * DI], cs);
            cs = fmaf(w3, xz_d[(size_t)t * 2 * DI], cs);
        } else {
            int base = LSEQ - 1 - t;
            cs = fmaf(w3, xz_d[(size_t)base * 2 * DI], cs);
            if (t >= 1) cs = fmaf(w2, xz_d[(size_t)(base + 1) * 2 * DI], cs);
            if (t >= 2) cs = fmaf(w1, xz_d[(size_t)(base + 2) * 2 * DI], cs);
            if (t >= 3) cs = fmaf(w0, xz_d[(size_t)(base + 3) * 2 * DI], cs);
        }
        float xv = siluf(cs);

        size_t r = r0 + t;
        const float4* dbq = (const float4*)(g_dbl + r * XD);
        float4 q0 = __ldg(dbq + 0), q1 = __ldg(dbq + 1), q2 = __ldg(dbq + 2);
        float4 qB0 = __ldg(dbq + 3), qB1 = __ldg(dbq + 4),
               qB2 = __ldg(dbq + 5), qB3 = __ldg(dbq + 6);
        float4 qC0 = __ldg(dbq + 7), qC1 = __ldg(dbq + 8),
               qC2 = __ldg(dbq + 9), qC3 = __ldg(dbq + 10);
        float d1 = db0, d2 = 0.f;
        d1 = fmaf(q0.x, wdt[0], d1); d2 = fmaf(q0.y, wdt[1], d2);
        d1 = fmaf(q0.z, wdt[2], d1); d2 = fmaf(q0.w, wdt[3], d2);
        d1 = fmaf(q1.x, wdt[4], d1); d2 = fmaf(q1.y, wdt[5], d2);
        d1 = fmaf(q1.z, wdt[6], d1); d2 = fmaf(q1.w, wdt[7], d2);
        d1 = fmaf(q2.x, wdt[8], d1); d2 = fmaf(q2.y, wdt[9], d2);
        d1 = fmaf(q2.z, wdt[10], d1); d2 = fmaf(q2.w, wdt[11], d2);
        float dt = softplusf(d1 + d2);
        float dtx = dt * xv;
        S += dt;
        float Bv[DS] = {qB0.x, qB0.y, qB0.z, qB0.w, qB1.x, qB1.y, qB1.z, qB1.w,
                        qB2.x, qB2.y, qB2.z, qB2.w, qB3.x, qB3.y, qB3.z, qB3.w};
        float Cv[DS] = {qC0.x, qC0.y, qC0.z, qC0.w, qC1.x, qC1.y, qC1.z, qC1.w,
                        qC2.x, qC2.y, qC2.z, qC2.w, qC3.x, qC3.y, qC3.z, qC3.w};
        float acc = 0.f;
        if (flag) {
            float e = __expf(dt * A0);
            float p = e;
#pragma unroll
            for (int n = 0; n < DS; n++) {
                h[n] = fmaf(p, h[n], dtx * Bv[n]);
                acc = fmaf(h[n], Cv[n], acc);
                p *= e;
            }
        } else {
#pragma unroll
            for (int n = 0; n < DS; n++) {
                float a = __expf(dt * A[n]);
                h[n] = fmaf(a, h[n], dtx * Bv[n]);
                acc = fmaf(h[n], Cv[n], acc);
            }
        }
        g_y[r * DI + d] = acc + xv * Dd;
    }
    size_t cb_ = ((size_t)dir * BATCH + b) * NC + c;
#pragma unroll
    for (int n = 0; n < DS; n++) g_hloc[(cb_ * DS + n) * DI + d] = h[n];
    g_S[cb_ * DI + d] = S;
}

// ---------------- scan pass C: carry-in reconstruction + fixup ---------------
__global__ __launch_bounds__(DI)
void k_scanC(const float* __restrict__ dtw, const float* __restrict__ dtb, int l) {
    int dir = blockIdx.z, b = blockIdx.y, c = blockIdx.x + 1;
    int d = threadIdx.x;
    const float* Ap = g_Aexp + (((size_t)dir * DEPTH + l) * DI + d) * DS;
    float A[DS];
#pragma unroll
    for (int n = 0; n < DS; n++) A[n] = Ap[n];
    int flag = g_Aflag[((size_t)dir * DEPTH + l) * DI + d];
    float A0 = A[0];
    float wdt[DR];
#pragma unroll
    for (int j = 0; j < DR; j++) wdt[j] = __ldg(dtw + (size_t)d * DR + j);
    float db0 = dtb[d];

    size_t cb0 = ((size_t)dir * BATCH + b) * NC;
    float g[DS];
#pragma unroll
    for (int n = 0; n < DS; n++) g[n] = 0.f;
    for (int cc = 0; cc < c; cc++) {
        float Sc = g_S[(cb0 + cc) * DI + d];
        if (flag) {
            float e = __expf(A0 * Sc);
            float p = e;
#pragma unroll
            for (int n = 0; n < DS; n++) {
                g[n] = fmaf(p, g[n], g_hloc[((cb0 + cc) * DS + n) * DI + d]);
                p *= e;
            }
        } else {
#pragma unroll
            for (int n = 0; n < DS; n++)
                g[n] = fmaf(__expf(A[n] * Sc), g[n],
                            g_hloc[((cb0 + cc) * DS + n) * DI + d]);
        }
    }

    size_t r0 = ((size_t)dir * BATCH + b) * LSEQ;
    int t0 = c * CL, t1 = min(LSEQ, t0 + CL);
    for (int t = t0; t < t1; t++) {
        size_t r = r0 + t;
        const float4* dbq = (const float4*)(g_dbl + r * XD);
        float4 q0 = __ldg(dbq + 0), q1 = __ldg(dbq + 1), q2 = __ldg(dbq + 2);
        float4 qC0 = __ldg(dbq + 7), qC1 = __ldg(dbq + 8),
               qC2 = __ldg(dbq + 9), qC3 = __ldg(dbq + 10);
        float d1 = db0, d2 = 0.f;
        d1 = fmaf(q0.x, wdt[0], d1); d2 = fmaf(q0.y, wdt[1], d2);
        d1 = fmaf(q0.z, wdt[2], d1); d2 = fmaf(q0.w, wdt[3], d2);
        d1 = fmaf(q1.x, wdt[4], d1); d2 = fmaf(q1.y, wdt[5], d2);
        d1 = fmaf(q1.z, wdt[6], d1); d2 = fmaf(q1.w, wdt[7], d2);
        d1 = fmaf(q2.x, wdt[8], d1); d2 = fmaf(q2.y, wdt[9], d2);
        d1 = fmaf(q2.z, wdt[10], d1); d2 = fmaf(q2.w, wdt[11], d2);
        float dt = softplusf(d1 + d2);
        float Cv[DS] = {qC0.x, qC0.y, qC0.z, qC0.w, qC1.x, qC1.y, qC1.z, qC1.w,
                        qC2.x, qC2.y, qC2.z, qC2.w, qC3.x, qC3.y, qC3.z, qC3.w};
        float acc = 0.f;
        if (flag) {
            float e = __expf(dt * A0);
            float p = e;
#pragma unroll
            for (int n = 0; n < DS; n++) {
                g[n] *= p;
                acc = fmaf(g[n], Cv[n], acc);
                p *= e;
            }
        } else {
#pragma unroll
            for (int n = 0; n < DS; n++) {
                g[n] *= __expf(dt * A[n]);
                acc = fmaf(g[n], Cv[n], acc);
            }
        }
        g_y[r * DI + d] += acc;
    }
}

// ---------------- final head: hn(token0) @ head^T + bias ---------------------
__global__ void k_final(const float* __restrict__ hw, const float* __restrict__ hb,
                        float* __restrict__ out) {
    int b = blockIdx.x;
    int c = threadIdx.x;
    if (c >= NCLS) return;
    const float* row = g_hn + (size_t)b * LSEQ * DM;   // token 0 already normalized
    float acc = hb[c];
    for (int j = 0; j < DM; j++) acc = fmaf(row[j], hw[(size_t)c * DM + j], acc);
    out[b * NCLS + c] = acc;
}

// ---------------- host --------------------------------------------------------
static float* symaddr(const void* sym) {
    void* p = nullptr;
    cudaGetSymbolAddress(&p, sym);
    return (float*)p;
}

extern "C" void kernel_launch(void* const* d_in, const int* in_sizes, int n_in,
                              void* d_out, int out_size) {
    (void)in_sizes; (void)n_in; (void)out_size;
    const float* x      = (const float*)d_in[0];
    const float* pe_w   = (const float*)d_in[1];
    const float* pe_b   = (const float*)d_in[2];
    const float* cls    = (const float*)d_in[3];
    const float* pos    = (const float*)d_in[4];
    const float* norm_w = (const float*)d_in[5];
    const float* ipw    = (const float*)d_in[6];
    const float* cw     = (const float*)d_in[7];
    const float* cb     = (const float*)d_in[8];
    const float* xpw    = (const float*)d_in[9];
    const float* dtw    = (const float*)d_in[10];
    const float* dtb    = (const float*)d_in[11];
    const float* Alog   = (const float*)d_in[12];
    const float* Ablog  = (const float*)d_in[13];
    const float* Dp     = (const float*)d_in[14];
    const float* opw    = (const float*)d_in[15];
    const float* nfw    = (const float*)d_in[16];
    const float* hw     = (const float*)d_in[17];
    const float* hb     = (const float*)d_in[18];
    float* out = (float*)d_out;

    float* p_hn  = symaddr(g_hn);
    float* p_xz  = symaddr(g_xz);
    float* p_cwT = symaddr(g_cwT);

    k_prep<<<(2 * DEPTH * DI + 127) / 128, 128>>>(Alog, Ablog, cw);
    k_embed<<<dim3(LSEQ, BATCH), DM>>>(x, pe_w, pe_b, cls, pos, norm_w);

    for (int l = 0; l < DEPTH; l++) {
        // xz = hn @ ipw^T : M=1604, N=768, K=192
        sgemm_nt<64, 64, 16, 4, 4><<<dim3((2 * DI) / 64, (ROWS + 63) / 64), 256>>>(
            p_hn, ipw + (size_t)l * 2 * DI * DM, p_xz, ROWS, 2 * DI, DM);

        // dbl = silu(conv(x-part)) @ xpw^T (conv fused into A-load)
        k_gemm_dbl<<<dim3(1, (ROWS2 + DB_BM - 1) / DB_BM), 256>>>(
            xpw + (size_t)l * XD * DI, p_cwT + (size_t)l * 4 * DI,
            cb + (size_t)l * DI);

        k_scanA<<<dim3(NC, BATCH, 2), DI>>>(dtw + (size_t)l * DI * DR,
                                            dtb + (size_t)l * DI,
                                            Dp + (size_t)l * DI,
                                            cw + (size_t)l * DI * 4,
                                            cb + (size_t)l * DI, l);
        k_scanC<<<dim3(NC - 1, BATCH, 2), DI>>>(dtw + (size_t)l * DI * DR,
                                                dtb + (size_t)l * DI, l);

        // hid = gated @ opw^T, epilogue: res += hid, hn = rmsnorm(res)*w_next
        const float* nw_next = (l == DEPTH - 1) ? nfw : (norm_w + (size_t)(l + 1) * DM);
        k_gemm_out<<<dim3(1, (ROWS + OG_BM - 1) / OG_BM), 256>>>(
            opw + (size_t)l * DM * DI, nw_next);
    }

    k_final<<<BATCH, 32>>>(hw, hb, out);
}

// round 3
// speedup vs baseline: 1.1878x; 1.1878x over previous
#include <cuda_runtime.h>
#include <math.h>

#define DEPTH 24
#define DM    192
#define DI    384
#define DS    16
#define DR    12
#define BATCH 4
#define LSEQ  401
#define NCLS  22
#define XD    44
#define EPSV  1e-5f
#define NC    31
#define CL    13
#define ROWS  (BATCH*LSEQ)     // 1604
#define ROWS2 (2*BATCH*LSEQ)   // 3208

// ---------------- scratch ----------------------------------------------------
__device__ float g_res [ROWS*DM];
__device__ float g_hid [ROWS*DM];
__device__ float g_hn  [ROWS*DM];
__device__ float g_xz  [ROWS*2*DI];
__device__ float g_xx  [ROWS2*DI];
__device__ float g_dbl [ROWS2*XD];
__device__ float g_y   [ROWS2*DI];
__device__ float g_Aexp[2*DEPTH*DI*DS];
__device__ int   g_Aflag[2*DEPTH*DI];
__device__ float g_hloc[2*BATCH*NC*DS*DI];
__device__ float g_S   [2*BATCH*NC*DI];

__device__ __forceinline__ float siluf(float x) { return x / (1.f + __expf(-x)); }
__device__ __forceinline__ float softplusf(float x) {
    return x > 20.f ? x : log1pf(__expf(x));
}

// ---------------- prep: A = -exp(A_log); detect geometric structure ----------
__global__ void k_prepA(const float* __restrict__ Alog, const float* __restrict__ Ablog) {
    int i = blockIdx.x * blockDim.x + threadIdx.x;
    if (i >= 2 * DEPTH * DI) return;
    int dir = i / (DEPTH * DI);
    int rest = i - dir * (DEPTH * DI);
    const float* src = (dir ? Ablog : Alog) + (size_t)rest * DS;
    float A[DS];
#pragma unroll
    for (int n = 0; n < DS; n++) A[n] = -__expf(src[n]);
    float A0 = A[0];
    bool ok = true;
#pragma unroll
    for (int n = 1; n < DS; n++) {
        float tgt = (float)(n + 1) * A0;
        ok = ok && (fabsf(A[n] - tgt) <= 1e-4f * fabsf(tgt) + 1e-30f);
    }
#pragma unroll
    for (int n = 0; n < DS; n++) g_Aexp[(size_t)i * DS + n] = A[n];
    g_Aflag[i] = ok ? 1 : 0;
}

// ---------------- patch embed + cls + pos ------------------------------------
__global__ void k_embed(const float* __restrict__ x, const float* __restrict__ pew,
                        const float* __restrict__ peb, const float* __restrict__ cls,
                        const float* __restrict__ pos) {
    int t = blockIdx.x, b = blockIdx.y, c = threadIdx.x;
    float v;
    __shared__ float patch[256];
    if (t == 0) {
        v = cls[c] + pos[c];
    } else {
        int p = t - 1;
        int ph = p / 200, pw = p % 200;
        for (int i = c; i < 256; i += DM)
            patch[i] = x[(size_t)b * 32 * 3200 + (size_t)(ph * 16 + i / 16) * 3200
                         + pw * 16 + (i % 16)];
        __syncthreads();
        float acc = peb[c];
        const float* wc = pew + (size_t)c * 256;
#pragma unroll 8
        for (int i = 0; i < 256; i++) acc = fmaf(patch[i], __ldg(wc + i), acc);
        v = acc + pos[(size_t)t * DM + c];
    }
    size_t o = ((size_t)b * LSEQ + t) * DM + c;
    g_res[o] = v;
    g_hid[o] = v;
}

// ---------------- residual += hidden; rmsnorm --------------------------------
__global__ void k_resnorm(const float* __restrict__ nw) {
    int r = blockIdx.x;
    int c = threadIdx.x;
    __shared__ float red[6];
    size_t o = (size_t)r * DM + c;
    float v = g_res[o] + g_hid[o];
    g_res[o] = v;
    float s = v * v;
#pragma unroll
    for (int ofs = 16; ofs > 0; ofs >>= 1) s += __shfl_xor_sync(0xffffffffu, s, ofs);
    if ((c & 31) == 0) red[c >> 5] = s;
    __syncthreads();
    float tot = red[0] + red[1] + red[2] + red[3] + red[4] + red[5];
    float rs = rsqrtf(tot / (float)DM + EPSV);
    g_hn[o] = v * rs * nw[c];
}

// ---------------- generic SGEMM: C[M,N] = A[M,K] @ W[N,K]^T ------------------
template <int BM, int BN, int BK, int TM, int TN>
__global__ __launch_bounds__((BM / TM) * (BN / TN))
void sgemm_nt(const float* __restrict__ A, const float* __restrict__ W,
              float* __restrict__ C, int M, int N, int K) {
    constexpr int THR = (BM / TM) * (BN / TN);
    __shared__ float As[BK][BM + 4];
    __shared__ float Ws[BK][BN + 4];
    int tid = threadIdx.x;
    int tx = tid % (BN / TN);
    int ty = tid / (BN / TN);
    int row0 = blockIdx.y * BM;
    int col0 = blockIdx.x * BN;
    float acc[TM][TN];
#pragma unroll
    for (int i = 0; i < TM; i++)
#pragma unroll
        for (int j = 0; j < TN; j++) acc[i][j] = 0.f;

    for (int k0 = 0; k0 < K; k0 += BK) {
        for (int i = tid; i < BM * (BK / 4); i += THR) {
            int m = i / (BK / 4), kq = i % (BK / 4);
            float4 v = make_float4(0.f, 0.f, 0.f, 0.f);
            if (row0 + m < M)
                v = __ldg((const float4*)(A + (size_t)(row0 + m) * K + k0 + kq * 4));
            As[kq * 4 + 0][m] = v.x; As[kq * 4 + 1][m] = v.y;
            As[kq * 4 + 2][m] = v.z; As[kq * 4 + 3][m] = v.w;
        }
        for (int i = tid; i < BN * (BK / 4); i += THR) {
            int n = i / (BK / 4), kq = i % (BK / 4);
            float4 v = make_float4(0.f, 0.f, 0.f, 0.f);
            if (col0 + n < N)
                v = __ldg((const float4*)(W + (size_t)(col0 + n) * K + k0 + kq * 4));
            Ws[kq * 4 + 0][n] = v.x; Ws[kq * 4 + 1][n] = v.y;
            Ws[kq * 4 + 2][n] = v.z; Ws[kq * 4 + 3][n] = v.w;
        }
        __syncthreads();
#pragma unroll
        for (int k = 0; k < BK; k++) {
            float ra[TM], rb[TN];
#pragma unroll
            for (int i = 0; i < TM; i++) ra[i] = As[k][ty * TM + i];
#pragma unroll
            for (int j = 0; j < TN; j++) rb[j] = Ws[k][tx * TN + j];
#pragma unroll
            for (int i = 0; i < TM; i++)
#pragma unroll
                for (int j = 0; j < TN; j++) acc[i][j] = fmaf(ra[i], rb[j], acc[i][j]);
        }
        __syncthreads();
    }
#pragma unroll
    for (int i = 0; i < TM; i++) {
        int r = row0 + ty * TM + i;
        if (r >= M) continue;
#pragma unroll
        for (int j = 0; j < TN; j++) {
            int cc = col0 + tx * TN + j;
            if (cc < N) C[(size_t)r * N + cc] = acc[i][j];
        }
    }
}

// ---------------- out_proj GEMM with gated A: A = (yf+yb)*silu(z) ------------
#define OP_BM 32
#define OP_BN 64
#define OP_BK 16
__global__ __launch_bounds__(256)
void k_gemm_out(const float* __restrict__ W) {
    __shared__ float As[OP_BK][OP_BM + 4];
    __shared__ float Ws[OP_BK][OP_BN + 4];
    int tid = threadIdx.x;
    int tx = tid % 16;            // BN/TN = 64/4
    int ty = tid / 16;            // BM/TM = 32/2
    int row0 = blockIdx.y * OP_BM;
    int col0 = blockIdx.x * OP_BN;
    float acc[2][4] = {};

    for (int k0 = 0; k0 < DI; k0 += OP_BK) {
        if (tid < OP_BM * (OP_BK / 4)) {         // 128 loader tasks
            int m = tid / 4, kq = tid % 4;
            int r = row0 + m;
            float4 a = make_float4(0.f, 0.f, 0.f, 0.f);
            if (r < ROWS) {
                int b = r / LSEQ, t = r % LSEQ;
                int d0 = k0 + kq * 4;
                float4 yf = __ldg((const float4*)(g_y + (size_t)r * DI + d0));
                size_t rb = ((size_t)(BATCH + b) * LSEQ + (LSEQ - 1 - t));
                float4 yb = __ldg((const float4*)(g_y + rb * DI + d0));
                float4 z4 = __ldg((const float4*)(g_xz + (size_t)r * 2 * DI + DI + d0));
                a.x = (yf.x + yb.x) * siluf(z4.x);
                a.y = (yf.y + yb.y) * siluf(z4.y);
                a.z = (yf.z + yb.z) * siluf(z4.z);
                a.w = (yf.w + yb.w) * siluf(z4.w);
            }
            As[kq * 4 + 0][m] = a.x; As[kq * 4 + 1][m] = a.y;
            As[kq * 4 + 2][m] = a.z; As[kq * 4 + 3][m] = a.w;
        }
        for (int i = tid; i < OP_BN * (OP_BK / 4); i += 256) {   // 256 tasks
            int n = i / 4, kq = i % 4;
            float4 v = __ldg((const float4*)(W + (size_t)(col0 + n) * DI + k0 + kq * 4));
            Ws[kq * 4 + 0][n] = v.x; Ws[kq * 4 + 1][n] = v.y;
            Ws[kq * 4 + 2][n] = v.z; Ws[kq * 4 + 3][n] = v.w;
        }
        __syncthreads();
#pragma unroll
        for (int k = 0; k < OP_BK; k++) {
            float ra0 = As[k][ty * 2 + 0], ra1 = As[k][ty * 2 + 1];
            float rb[4];
#pragma unroll
            for (int j = 0; j < 4; j++) rb[j] = Ws[k][tx * 4 + j];
#pragma unroll
            for (int j = 0; j < 4; j++) {
                acc[0][j] = fmaf(ra0, rb[j], acc[0][j]);
                acc[1][j] = fmaf(ra1, rb[j], acc[1][j]);
            }
        }
        __syncthreads();
    }
#pragma unroll
    for (int i = 0; i < 2; i++) {
        int r = row0 + ty * 2 + i;
        if (r >= ROWS) continue;
#pragma unroll
        for (int j = 0; j < 4; j++)
            g_hid[(size_t)r * DM + col0 + tx * 4 + j] = acc[i][j];
    }
}

// ---------------- causal depthwise conv + silu (both directions) -------------
#define CONV_TT 16
__global__ void k_conv(const float* __restrict__ cw, const float* __restrict__ cb) {
    int dir = blockIdx.z, b = blockIdx.y, tile = blockIdx.x;
    int d = threadIdx.x;
    float w0 = cw[d * 4 + 0], w1 = cw[d * 4 + 1], w2 = cw[d * 4 + 2], w3 = cw[d * 4 + 3];
    float bi = cb[d];
    const float* xzb = g_xz + (size_t)b * LSEQ * 2 * DI + d;
    int t0 = tile * CONV_TT, t1 = min(LSEQ, t0 + CONV_TT);
    for (int t = t0; t < t1; t++) {
        float s = bi;
        if (dir == 0) {
            if (t >= 3) s = fmaf(w0, xzb[(size_t)(t - 3) * 2 * DI], s);
            if (t >= 2) s = fmaf(w1, xzb[(size_t)(t - 2) * 2 * DI], s);
            if (t >= 1) s = fmaf(w2, xzb[(size_t)(t - 1) * 2 * DI], s);
            s = fmaf(w3, xzb[(size_t)t * 2 * DI], s);
        } else {
            int base = LSEQ - 1 - t;
            s = fmaf(w3, xzb[(size_t)base * 2 * DI], s);
            if (t >= 1) s = fmaf(w2, xzb[(size_t)(base + 1) * 2 * DI], s);
            if (t >= 2) s = fmaf(w1, xzb[(size_t)(base + 2) * 2 * DI], s);
            if (t >= 3) s = fmaf(w0, xzb[(size_t)(base + 3) * 2 * DI], s);
        }
        g_xx[(((size_t)dir * BATCH + b) * LSEQ + t) * DI + d] = siluf(s);
    }
}

// ---------------- scan pass A: chunk-local scan (dt_proj fused) --------------
__global__ __launch_bounds__(DI)
void k_scanA(const float* __restrict__ dtw, const float* __restrict__ dtb,
             const float* __restrict__ Dpl, int l) {
    int dir = blockIdx.z, b = blockIdx.y, c = blockIdx.x;
    int d = threadIdx.x;
    const float* Ap = g_Aexp + (((size_t)dir * DEPTH + l) * DI + d) * DS;
    float A[DS];
#pragma unroll
    for (int n = 0; n < DS; n++) A[n] = Ap[n];
    int flag = g_Aflag[((size_t)dir * DEPTH + l) * DI + d];
    float A0 = A[0];
    float wdt[DR];
#pragma unroll
    for (int j = 0; j < DR; j++) wdt[j] = __ldg(dtw + (size_t)d * DR + j);
    float db0 = dtb[d], Dd = Dpl[d];

    size_t r0 = ((size_t)dir * BATCH + b) * LSEQ;
    int t0 = c * CL, t1 = min(LSEQ, t0 + CL);
    float h[DS];
#pragma unroll
    for (int n = 0; n < DS; n++) h[n] = 0.f;
    float S = 0.f;

    for (int t = t0; t < t1; t++) {
        size_t r = r0 + t;
        const float4* dbq = (const float4*)(g_dbl + r * XD);
        float4 q0 = __ldg(dbq + 0), q1 = __ldg(dbq + 1), q2 = __ldg(dbq + 2);
        float4 qB0 = __ldg(dbq + 3), qB1 = __ldg(dbq + 4),
               qB2 = __ldg(dbq + 5), qB3 = __ldg(dbq + 6);
        float4 qC0 = __ldg(dbq + 7), qC1 = __ldg(dbq + 8),
               qC2 = __ldg(dbq + 9), qC3 = __ldg(dbq + 10);
        float d1 = db0, d2 = 0.f;
        d1 = fmaf(q0.x, wdt[0], d1); d2 = fmaf(q0.y, wdt[1], d2);
        d1 = fmaf(q0.z, wdt[2], d1); d2 = fmaf(q0.w, wdt[3], d2);
        d1 = fmaf(q1.x, wdt[4], d1); d2 = fmaf(q1.y, wdt[5], d2);
        d1 = fmaf(q1.z, wdt[6], d1); d2 = fmaf(q1.w, wdt[7], d2);
        d1 = fmaf(q2.x, wdt[8], d1); d2 = fmaf(q2.y, wdt[9], d2);
        d1 = fmaf(q2.z, wdt[10], d1); d2 = fmaf(q2.w, wdt[11], d2);
        float dt = softplusf(d1 + d2);
        float xv = g_xx[r * DI + d];
        float dtx = dt * xv;
        S += dt;
        float Bv[DS] = {qB0.x, qB0.y, qB0.z, qB0.w, qB1.x, qB1.y, qB1.z, qB1.w,
                        qB2.x, qB2.y, qB2.z, qB2.w, qB3.x, qB3.y, qB3.z, qB3.w};
        float Cv[DS] = {qC0.x, qC0.y, qC0.z, qC0.w, qC1.x, qC1.y, qC1.z, qC1.w,
                        qC2.x, qC2.y, qC2.z, qC2.w, qC3.x, qC3.y, qC3.z, qC3.w};
        float acc = 0.f;
        if (flag) {
            float e = __expf(dt * A0);
            float p = e;
#pragma unroll
            for (int n = 0; n < DS; n++) {
                h[n] = fmaf(p, h[n], dtx * Bv[n]);
                acc = fmaf(h[n], Cv[n], acc);
                p *= e;
            }
        } else {
#pragma unroll
            for (int n = 0; n < DS; n++) {
                float a = __expf(dt * A[n]);
                h[n] = fmaf(a, h[n], dtx * Bv[n]);
                acc = fmaf(h[n], Cv[n], acc);
            }
        }
        g_y[r * DI + d] = acc + xv * Dd;
    }
    size_t cb_ = ((size_t)dir * BATCH + b) * NC + c;
#pragma unroll
    for (int n = 0; n < DS; n++) g_hloc[(cb_ * DS + n) * DI + d] = h[n];
    g_S[cb_ * DI + d] = S;
}

// ---------------- scan pass C: carry-in reconstruction + fixup ---------------
__global__ __launch_bounds__(DI)
void k_scanC(const float* __restrict__ dtw, const float* __restrict__ dtb, int l) {
    int dir = blockIdx.z, b = blockIdx.y, c = blockIdx.x + 1;
    int d = threadIdx.x;
    const float* Ap = g_Aexp + (((size_t)dir * DEPTH + l) * DI + d) * DS;
    float A[DS];
#pragma unroll
    for (int n = 0; n < DS; n++) A[n] = Ap[n];
    int flag = g_Aflag[((size_t)dir * DEPTH + l) * DI + d];
    float A0 = A[0];
    float wdt[DR];
#pragma unroll
    for (int j = 0; j < DR; j++) wdt[j] = __ldg(dtw + (size_t)d * DR + j);
    float db0 = dtb[d];

    size_t cb0 = ((size_t)dir * BATCH + b) * NC;
    float g[DS];
#pragma unroll
    for (int n = 0; n < DS; n++) g[n] = 0.f;
    for (int cc = 0; cc < c; cc++) {
        float Sc = g_S[(cb0 + cc) * DI + d];
        if (flag) {
            float e = __expf(A0 * Sc);
            float p = e;
#pragma unroll
            for (int n = 0; n < DS; n++) {
                g[n] = fmaf(p, g[n], g_hloc[((cb0 + cc) * DS + n) * DI + d]);
                p *= e;
            }
        } else {
#pragma unroll
            for (int n = 0; n < DS; n++)
                g[n] = fmaf(__expf(A[n] * Sc), g[n],
                            g_hloc[((cb0 + cc) * DS + n) * DI + d]);
        }
    }

    size_t r0 = ((size_t)dir * BATCH + b) * LSEQ;
    int t0 = c * CL, t1 = min(LSEQ, t0 + CL);
    for (int t = t0; t < t1; t++) {
        size_t r = r0 + t;
        const float4* dbq = (const float4*)(g_dbl + r * XD);
        float4 q0 = __ldg(dbq + 0), q1 = __ldg(dbq + 1), q2 = __ldg(dbq + 2);
        float4 qC0 = __ldg(dbq + 7), qC1 = __ldg(dbq + 8),
               qC2 = __ldg(dbq + 9), qC3 = __ldg(dbq + 10);
        float d1 = db0, d2 = 0.f;
        d1 = fmaf(q0.x, wdt[0], d1); d2 = fmaf(q0.y, wdt[1], d2);
        d1 = fmaf(q0.z, wdt[2], d1); d2 = fmaf(q0.w, wdt[3], d2);
        d1 = fmaf(q1.x, wdt[4], d1); d2 = fmaf(q1.y, wdt[5], d2);
        d1 = fmaf(q1.z, wdt[6], d1); d2 = fmaf(q1.w, wdt[7], d2);
        d1 = fmaf(q2.x, wdt[8], d1); d2 = fmaf(q2.y, wdt[9], d2);
        d1 = fmaf(q2.z, wdt[10], d1); d2 = fmaf(q2.w, wdt[11], d2);
        float dt = softplusf(d1 + d2);
        float Cv[DS] = {qC0.x, qC0.y, qC0.z, qC0.w, qC1.x, qC1.y, qC1.z, qC1.w,
                        qC2.x, qC2.y, qC2.z, qC2.w, qC3.x, qC3.y, qC3.z, qC3.w};
        float acc = 0.f;
        if (flag) {
            float e = __expf(dt * A0);
            float p = e;
#pragma unroll
            for (int n = 0; n < DS; n++) {
                g[n] *= p;
                acc = fmaf(g[n], Cv[n], acc);
                p *= e;
            }
        } else {
#pragma unroll
            for (int n = 0; n < DS; n++) {
                g[n] *= __expf(dt * A[n]);
                acc = fmaf(g[n], Cv[n], acc);
            }
        }
        g_y[r * DI + d] += acc;
    }
}

// ---------------- final: norm token 0 + head ---------------------------------
__global__ void k_final(const float* __restrict__ nfw, const float* __restrict__ hw,
                        const float* __restrict__ hb, float* __restrict__ out) {
    int b = blockIdx.x;
    int c = threadIdx.x;
    __shared__ float vn[DM];
    __shared__ float red[6];
    size_t o = ((size_t)b * LSEQ) * DM + c;
    float v = g_res[o] + g_hid[o];
    float s = v * v;
#pragma unroll
    for (int ofs = 16; ofs > 0; ofs >>= 1) s += __shfl_xor_sync(0xffffffffu, s, ofs);
    if ((c & 31) == 0) red[c >> 5] = s;
    __syncthreads();
    float tot = red[0] + red[1] + red[2] + red[3] + red[4] + red[5];
    float rs = rsqrtf(tot / (float)DM + EPSV);
    vn[c] = v * rs * nfw[c];
    __syncthreads();
    if (c < NCLS) {
        float acc = hb[c];
        for (int j = 0; j < DM; j++) acc = fmaf(vn[j], hw[(size_t)c * DM + j], acc);
        out[b * NCLS + c] = acc;
    }
}

// ---------------- host --------------------------------------------------------
static float* symaddr(const void* sym) {
    void* p = nullptr;
    cudaGetSymbolAddress(&p, sym);
    return (float*)p;
}

extern "C" void kernel_launch(void* const* d_in, const int* in_sizes, int n_in,
                              void* d_out, int out_size) {
    (void)in_sizes; (void)n_in; (void)out_size;
    const float* x      = (const float*)d_in[0];
    const float* pe_w   = (const float*)d_in[1];
    const float* pe_b   = (const float*)d_in[2];
    const float* cls    = (const float*)d_in[3];
    const float* pos    = (const float*)d_in[4];
    const float* norm_w = (const float*)d_in[5];
    const float* ipw    = (const float*)d_in[6];
    const float* cw     = (const float*)d_in[7];
    const float* cb     = (const float*)d_in[8];
    const float* xpw    = (const float*)d_in[9];
    const float* dtw    = (const float*)d_in[10];
    const float* dtb    = (const float*)d_in[11];
    const float* Alog   = (const float*)d_in[12];
    const float* Ablog  = (const float*)d_in[13];
    const float* Dp     = (const float*)d_in[14];
    const float* opw    = (const float*)d_in[15];
    const float* nfw    = (const float*)d_in[16];
    const float* hw     = (const float*)d_in[17];
    const float* hb     = (const float*)d_in[18];
    float* out = (float*)d_out;

    float* p_hn  = symaddr(g_hn);
    float* p_xz  = symaddr(g_xz);
    float* p_xx  = symaddr(g_xx);
    float* p_dbl = symaddr(g_dbl);

    k_prepA<<<(2 * DEPTH * DI + 127) / 128, 128>>>(Alog, Ablog);
    k_embed<<<dim3(LSEQ, BATCH), DM>>>(x, pe_w, pe_b, cls, pos);

    for (int l = 0; l < DEPTH; l++) {
        k_resnorm<<<ROWS, DM>>>(norm_w + (size_t)l * DM);

        // xz = hn @ ipw^T : M=1604, N=768, K=192  (312 blocks)
        sgemm_nt<64, 64, 16, 4, 4><<<dim3((2 * DI) / 64, (ROWS + 63) / 64), 256>>>(
            p_hn, ipw + (size_t)l * 2 * DI * DM, p_xz, ROWS, 2 * DI, DM);

        k_conv<<<dim3((LSEQ + CONV_TT - 1) / CONV_TT, BATCH, 2), DI>>>(
            cw + (size_t)l * DI * 4, cb + (size_t)l * DI);

        // dbl = xx @ xpw^T : M=3208, N=44, K=384  (101 blocks)
        sgemm_nt<32, 64, 16, 2, 4><<<dim3(1, (ROWS2 + 31) / 32), 256>>>(
            p_xx, xpw + (size_t)l * XD * DI, p_dbl, ROWS2, XD, DI);

        k_scanA<<<dim3(NC, BATCH, 2), DI>>>(dtw + (size_t)l * DI * DR,
                                            dtb + (size_t)l * DI,
                                            Dp + (size_t)l * DI, l);
        k_scanC<<<dim3(NC - 1, BATCH, 2), DI>>>(dtw + (size_t)l * DI * DR,
                                                dtb + (size_t)l * DI, l);

        // hid = gated @ opw^T (gate fused into A-load)  (153 blocks)
        k_gemm_out<<<dim3(DM / OP_BN, (ROWS + OP_BM - 1) / OP_BM), 256>>>(
            opw + (size_t)l * DM * DI);
    }

    k_final<<<BATCH, DM>>>(nfw, hw, hb, out);
}